// round 9
// baseline (speedup 1.0000x reference)
#include <cuda_runtime.h>
#include <cstddef>

// ---------------- problem constants ----------------
#define BB   64
#define TT   1024
#define II   128
#define HH   512
#define KK   640            // I + H

// ---------------- partitioning ----------------
#define GH   32             // hidden groups
#define GB   4              // batch groups
#define NCTA (GH*GB)        // 128 CTAs, one per SM, all resident
#define UH   16             // hidden units per CTA
#define UB   16             // batches per CTA
#define NTHR 256            // 16 u x 4 bq x 4 ks

#define HXST 640            // hx row stride (floats): reads are broadcast, no pad needed
#define REDST 20            // reduction row stride (16 data + 4 pad floats)
#define KQ   40             // float4 chunks per k-quarter: 640/4/4

typedef unsigned long long ull;

// persistent state (no cudaMalloc allowed)
__device__ float    g_Hbuf[2][BB*HH];
__device__ unsigned g_bar[GB * 32];   // one counter per batch group, separate lines

// ---------------- packed fp32x2 helpers (Blackwell) ----------------
__device__ __forceinline__ ull ffma2(ull a, ull b, ull c) {
    ull d;
    asm("fma.rn.f32x2 %0, %1, %2, %3;" : "=l"(d) : "l"(a), "l"(b), "l"(c));
    return d;
}
__device__ __forceinline__ ull pack2(float lo, float hi) {
    ull d; asm("mov.b64 %0, {%1, %2};" : "=l"(d) : "f"(lo), "f"(hi)); return d;
}
__device__ __forceinline__ float red2(ull v) {
    return __uint_as_float((unsigned)v) + __uint_as_float((unsigned)(v >> 32));
}
__device__ __forceinline__ float sigm(float x) { return 1.0f / (1.0f + expf(-x)); }

__device__ __forceinline__ unsigned ld_acq(const unsigned* p) {
    unsigned v;
    asm volatile("ld.acquire.gpu.global.u32 %0, [%1];" : "=r"(v) : "l"(p) : "memory");
    return v;
}

__global__ void slstm_init_kernel() {
    if (threadIdx.x < GB) g_bar[threadIdx.x * 32] = 0u;
}

// ---------------- persistent sLSTM kernel ----------------
extern "C" __global__ void __launch_bounds__(NTHR, 1)
sLSTM_70772471103948_kernel(const float* __restrict__ x,     // [B,T,I]
                            const float* __restrict__ W_ih,  // [4H,I]
                            const float* __restrict__ W_hh,  // [4H,H]
                            const float* __restrict__ b_ih,  // [4H]
                            const float* __restrict__ b_hh,  // [4H]
                            const float* __restrict__ Wf,    // [H,H]
                            const float* __restrict__ bf,    // [H]
                            float* __restrict__ out,         // [B,T,H] | h[B,H] | c[B,H]
                            long long out_elems)
{
    extern __shared__ float smem[];
    // Wopt layout: float4 index = ((ks*KQ + kk)*4 + gate)*16 + u
    //   -> a warp (16 u-lanes x 2 ks) reads two contiguous 256B blocks per gate
    //      load: exactly 4 wavefronts, conflict-free.
    float* Wsm = smem;                           // 64*640 floats, exact (160 KB)
    float* hx  = smem + 64 * KK;                 // 16 batch rows x HXST ([x_t | h_t])
    float* red = hx + UB * HXST;                 // 256 rows x REDST (phase-1 partials)

    const int tid = threadIdx.x;
    const int u   = tid & 15;                    // local hidden unit
    const int q   = tid >> 4;                    // 0..15: owned local batch
    const int bq  = q >> 2;                      // phase-1 batch quad
    const int ks  = q & 3;                       // phase-1 k quarter (== owned slot)
    const int hg  = blockIdx.x & (GH - 1);
    const int bg  = blockIdx.x >> 5;
    const int j0  = hg * UH;
    const int b0  = bg * UB;
    const int j   = j0 + u;                      // global hidden index
    const int gb  = b0 + q;                      // global owned batch

    // ---- stage gate weights into SMEM once, in register-tile order ----
    for (int idx = tid; idx < 64 * KK; idx += NTHR) {
        int r  = idx / KK;                       // 0..63 (= g*16 + uu)
        int k  = idx - r * KK;                   // 0..639
        int g  = r >> 4, uu = r & 15;
        int grow = g * HH + j0 + uu;             // gate order: i,f,g,o
        float w = (k < II) ? W_ih[grow * II + k] : W_hh[grow * HH + (k - II)];
        int ksk = k / 160, kr = k - ksk * 160;
        int kkc = kr >> 2, e = kr & 3;
        Wsm[(((ksk * KQ + kkc) * 4 + g) * 16 + uu) * 4 + e] = w;
    }
    // ---- stage x_0 ; h_0 = 0 ----
    {
        const float4* xs = (const float4*)x;
        #pragma unroll
        for (int it = 0; it < (UB * II / 4) / NTHR; it++) {
            int idx = tid + it * NTHR;
            int b = idx >> 5, k4 = idx & 31;
            *(float4*)(hx + b * HXST + k4 * 4) =
                xs[((size_t)(b0 + b) * TT + 0) * (II / 4) + k4];
        }
        float4 z = make_float4(0.f, 0.f, 0.f, 0.f);
        #pragma unroll
        for (int it = 0; it < (UB * HH / 4) / NTHR; it++) {
            int idx = tid + it * NTHR;
            int b = idx >> 7, k4 = idx & 127;
            *(float4*)(hx + b * HXST + II + k4 * 4) = z;
        }
    }
    const float bias0 = b_ih[0 * HH + j] + b_hh[0 * HH + j];
    const float bias1 = b_ih[1 * HH + j] + b_hh[1 * HH + j];
    const float bias2 = b_ih[2 * HH + j] + b_hh[2 * HH + j];
    const float bias3 = b_ih[3 * HH + j] + b_hh[3 * HH + j];
    const float bfj = bf[j];

    __syncthreads();

    // phase-1 pointers
    const ulonglong2* Wq = (const ulonglong2*)Wsm + (size_t)ks * (KQ * 64) + u; // +g*16, +kk*64
    const ulonglong2* vP0 = (const ulonglong2*)(hx + (bq * 4 + 0) * HXST) + ks * KQ;
    const ulonglong2* vP1 = (const ulonglong2*)(hx + (bq * 4 + 1) * HXST) + ks * KQ;
    const ulonglong2* vP2 = (const ulonglong2*)(hx + (bq * 4 + 2) * HXST) + ks * KQ;
    const ulonglong2* vP3 = (const ulonglong2*)(hx + (bq * 4 + 3) * HXST) + ks * KQ;
    float* myred = red + (q * 16 + u) * REDST;
    const float4* wfrow = (const float4*)(Wf + (size_t)j * HH);
    const ulonglong2* hmine = (const ulonglong2*)(hx + q * HXST + II);
    unsigned* mybar = &g_bar[bg * 32];

    float cc = 0.f, hv_ = 0.f;                   // owned (j, gb) state

    #pragma unroll 1
    for (int t = 0; t < TT; t++) {
        // ===== phase 1: 4 gates x 4 batches over this thread's k-quarter =====
        ull a00 = 0, a01 = 0, a02 = 0, a03 = 0;
        ull a10 = 0, a11 = 0, a12 = 0, a13 = 0;
        ull a20 = 0, a21 = 0, a22 = 0, a23 = 0;
        ull a30 = 0, a31 = 0, a32 = 0, a33 = 0;
        #pragma unroll 2
        for (int kk = 0; kk < KQ; kk++) {
            const ulonglong2* wk = Wq + kk * 64;
            ulonglong2 w0 = wk[0], w1 = wk[16], w2 = wk[32], w3 = wk[48];
            ulonglong2 v0 = vP0[kk], v1 = vP1[kk], v2 = vP2[kk], v3 = vP3[kk];
            a00 = ffma2(w0.x, v0.x, a00); a00 = ffma2(w0.y, v0.y, a00);
            a01 = ffma2(w0.x, v1.x, a01); a01 = ffma2(w0.y, v1.y, a01);
            a02 = ffma2(w0.x, v2.x, a02); a02 = ffma2(w0.y, v2.y, a02);
            a03 = ffma2(w0.x, v3.x, a03); a03 = ffma2(w0.y, v3.y, a03);
            a10 = ffma2(w1.x, v0.x, a10); a10 = ffma2(w1.y, v0.y, a10);
            a11 = ffma2(w1.x, v1.x, a11); a11 = ffma2(w1.y, v1.y, a11);
            a12 = ffma2(w1.x, v2.x, a12); a12 = ffma2(w1.y, v2.y, a12);
            a13 = ffma2(w1.x, v3.x, a13); a13 = ffma2(w1.y, v3.y, a13);
            a20 = ffma2(w2.x, v0.x, a20); a20 = ffma2(w2.y, v0.y, a20);
            a21 = ffma2(w2.x, v1.x, a21); a21 = ffma2(w2.y, v1.y, a21);
            a22 = ffma2(w2.x, v2.x, a22); a22 = ffma2(w2.y, v2.y, a22);
            a23 = ffma2(w2.x, v3.x, a23); a23 = ffma2(w2.y, v3.y, a23);
            a30 = ffma2(w3.x, v0.x, a30); a30 = ffma2(w3.y, v0.y, a30);
            a31 = ffma2(w3.x, v1.x, a31); a31 = ffma2(w3.y, v1.y, a31);
            a32 = ffma2(w3.x, v2.x, a32); a32 = ffma2(w3.y, v2.y, a32);
            a33 = ffma2(w3.x, v3.x, a33); a33 = ffma2(w3.y, v3.y, a33);
        }
        // publish fp32 partials: one float4 per gate (4 batches)
        ((float4*)myred)[0] = make_float4(red2(a00), red2(a01), red2(a02), red2(a03));
        ((float4*)myred)[1] = make_float4(red2(a10), red2(a11), red2(a12), red2(a13));
        ((float4*)myred)[2] = make_float4(red2(a20), red2(a21), red2(a22), red2(a23));
        ((float4*)myred)[3] = make_float4(red2(a30), red2(a31), red2(a32), red2(a33));
        __syncthreads();                          // S1

        // ===== gather 4 k-quarter partials for owned (u, gb); activation =====
        float g0, g1, g2, g3;
        {
            const float* rp = red + (bq * 4 * 16 + u) * REDST + ks;  // ks == batch slot
            g0 = rp[0]; g1 = rp[4]; g2 = rp[8]; g3 = rp[12];
            #pragma unroll
            for (int kr = 1; kr < 4; kr++) {
                const float* r2 = rp + kr * 16 * REDST;
                g0 += r2[0]; g1 += r2[4]; g2 += r2[8]; g3 += r2[12];
            }
        }
        {
            float iv = sigm(g0 + bias0);
            float fv = sigm(g1 + bias1);
            float gv = tanhf(g2 + bias2);
            float ov = sigm(g3 + bias3);
            cc  = fv * cc + iv * gv;
            hv_ = ov * tanhf(cc);
        }
        const int p1 = (t + 1) & 1;
        out[((size_t)gb * TT + t) * HH + j] = hv_;
        __stcg(&g_Hbuf[p1][gb * HH + j], hv_);

        // prefetch x_{t+1} (independent of barrier; phase-1 reads finished at S1)
        if (t + 1 < TT) {
            const float4* xs = (const float4*)x;
            #pragma unroll
            for (int it = 0; it < (UB * II / 4) / NTHR; it++) {
                int idx = tid + it * NTHR;
                int b = idx >> 5, k4 = idx & 31;
                *(float4*)(hx + b * HXST + k4 * 4) =
                    xs[((size_t)(b0 + b) * TT + (t + 1)) * (II / 4) + k4];
            }
        }
        __syncthreads();                          // S2: all h stores issued CTA-wide

        // ===== per-batch-group grid barrier (32 CTAs) =====
        if (tid == 0) {
            __threadfence();                      // release h writes
            atomicAdd(mybar, 1u);
            const unsigned target = (unsigned)(t + 1) * GH;
            while (ld_acq(mybar) < target) { }
        }
        __syncthreads();                          // S3

        // ===== stage h_{t+1} into SMEM (vectorized) =====
        {
            const float4* hb = (const float4*)g_Hbuf[p1];
            #pragma unroll
            for (int it = 0; it < (UB * HH / 4) / NTHR; it++) {
                int idx = tid + it * NTHR;
                int b = idx >> 7, k4 = idx & 127;
                float4 v = __ldcg(&hb[(size_t)(b0 + b) * (HH / 4) + k4]);
                *(float4*)(hx + b * HXST + II + k4 * 4) = v;
            }
        }
        __syncthreads();                          // S4

        // ===== fe = exp(h_new @ Wf^T + bf); c *= fe  (owned batch, full k=512) =====
        {
            ull s0 = 0, s1 = 0;
            #pragma unroll 8
            for (int qk = 0; qk < HH / 4; qk++) {   // 128 iters x 4 floats = 512
                float4 w = __ldg(&wfrow[qk]);
                ulonglong2 hvv = hmine[qk];
                s0 = ffma2(pack2(w.x, w.y), hvv.x, s0);
                s1 = ffma2(pack2(w.z, w.w), hvv.y, s1);
            }
            cc *= expf(red2(s0) + red2(s1) + bfj);
        }
    }

    // ===== final h, c (tuple flatten: out | h | c) =====
    if (out_elems >= (long long)BB * TT * HH + 2LL * BB * HH) {
        float* hout = out + (size_t)BB * TT * HH;
        float* cout = hout + (size_t)BB * HH;
        hout[gb * HH + j] = hv_;
        cout[gb * HH + j] = cc;
    }
}

extern "C" void kernel_launch(void* const* d_in, const int* in_sizes, int n_in,
                              void* d_out, int out_size) {
    const float* x    = (const float*)d_in[0];
    const float* W_ih = (const float*)d_in[1];
    const float* W_hh = (const float*)d_in[2];
    const float* b_ih = (const float*)d_in[3];
    const float* b_hh = (const float*)d_in[4];
    const float* Wf   = (const float*)d_in[5];
    const float* bf   = (const float*)d_in[6];
    // d_in[7] = Wi, d_in[8] = bi: unused by the reference recurrence
    float* out = (float*)d_out;

    const size_t smem_bytes =
        (size_t)(64 * KK + UB * HXST + 256 * REDST) * sizeof(float); // 225,280 B
    cudaFuncSetAttribute(sLSTM_70772471103948_kernel,
                         cudaFuncAttributeMaxDynamicSharedMemorySize, (int)smem_bytes);

    slstm_init_kernel<<<1, 32>>>();
    sLSTM_70772471103948_kernel<<<NCTA, NTHR, smem_bytes>>>(
        x, W_ih, W_hh, b_ih, b_hh, Wf, bf, out, (long long)out_size);
}

// round 11
// speedup vs baseline: 1.4151x; 1.4151x over previous
#include <cuda_runtime.h>
#include <cstddef>

// ---------------- problem constants ----------------
#define BB   64
#define TT   1024
#define II   128
#define HH   512
#define KK   640            // I + H

// ---------------- partitioning ----------------
#define GH   32             // hidden groups
#define GB   4              // batch groups
#define NCTA (GH*GB)        // 128 CTAs, one per SM, all resident
#define UH   16             // hidden units per CTA
#define UB   16             // batches per CTA
#define NTHR 512            // 16 u x 8 bp x 4 ks  (16 warps, 4/SMSP)

#define WST  642            // weight row stride: 642%32==2 -> u-lanes cover all 32 banks
#define HXST 640            // hx row stride: 16B-aligned rows (reads are broadcast anyway)
#define REDST 9             // phase-1 partial row stride (8 data + 1 pad), scalar
#define KQ80 80             // ull (f32x2) elements per k-quarter: 640/2/4

typedef unsigned long long ull;

// persistent state (no cudaMalloc allowed)
__device__ float    g_Hbuf[2][BB*HH];
__device__ unsigned g_bar[GB * 32];   // one counter per batch group, separate lines

// ---------------- packed fp32x2 helpers (Blackwell) ----------------
__device__ __forceinline__ ull ffma2(ull a, ull b, ull c) {
    ull d;
    asm("fma.rn.f32x2 %0, %1, %2, %3;" : "=l"(d) : "l"(a), "l"(b), "l"(c));
    return d;
}
__device__ __forceinline__ ull pack2(float lo, float hi) {
    ull d; asm("mov.b64 %0, {%1, %2};" : "=l"(d) : "f"(lo), "f"(hi)); return d;
}
__device__ __forceinline__ float red2(ull v) {
    return __uint_as_float((unsigned)v) + __uint_as_float((unsigned)(v >> 32));
}
__device__ __forceinline__ float sigm(float x) { return 1.0f / (1.0f + expf(-x)); }

__device__ __forceinline__ unsigned ld_acq(const unsigned* p) {
    unsigned v;
    asm volatile("ld.acquire.gpu.global.u32 %0, [%1];" : "=r"(v) : "l"(p) : "memory");
    return v;
}

__global__ void slstm_init_kernel() {
    if (threadIdx.x < GB) g_bar[threadIdx.x * 32] = 0u;
}

// ---------------- persistent sLSTM kernel ----------------
extern "C" __global__ void __launch_bounds__(NTHR, 1)
sLSTM_70772471103948_kernel(const float* __restrict__ x,     // [B,T,I]
                            const float* __restrict__ W_ih,  // [4H,I]
                            const float* __restrict__ W_hh,  // [4H,H]
                            const float* __restrict__ b_ih,  // [4H]
                            const float* __restrict__ b_hh,  // [4H]
                            const float* __restrict__ Wf,    // [H,H]
                            const float* __restrict__ bf,    // [H]
                            float* __restrict__ out,         // [B,T,H] | h[B,H] | c[B,H]
                            long long out_elems)
{
    extern __shared__ float smem[];
    float* Wsm   = smem;                         // 64 rows x WST
    float* hx    = smem + 64 * WST;              // 16 batch rows x HXST ([x_t | h_t])
    float* red   = hx + UB * HXST;               // 3*128 rows x REDST (ks=1..3 partials)
    float* redfe = red + 3 * 128 * REDST;        // 3*128 x 2 fe partials

    const int tid = threadIdx.x;
    const int u   = tid & 15;                    // local hidden unit
    const int bp  = (tid >> 4) & 7;              // batch pair 0..7
    const int ks  = tid >> 7;                    // k quarter 0..3 (uniform per warp)
    const int hg  = blockIdx.x & (GH - 1);
    const int bg  = blockIdx.x >> 5;
    const int j0  = hg * UH;
    const int b0  = bg * UB;
    const int j   = j0 + u;                      // global hidden index
    const int blo = bp, bhi = bp + 8;
    const int gblo = b0 + blo, gbhi = b0 + bhi;

    // ---- stage gate weights into SMEM once ----
    for (int idx = tid; idx < 64 * KK; idx += NTHR) {
        int r  = idx / KK;
        int k  = idx - r * KK;
        int gg = r >> 4, uu = r & 15;
        int grow = gg * HH + j0 + uu;            // gate order: i,f,g,o
        float w = (k < II) ? W_ih[grow * II + k] : W_hh[grow * HH + (k - II)];
        Wsm[r * WST + k] = w;
    }
    // ---- stage x_0 ; h_0 = 0 ----
    {
        const float4* xs = (const float4*)x;
        {
            int idx = tid;                        // UB*II/4 = 512 = NTHR
            int b = idx >> 5, k4 = idx & 31;
            *(float4*)(hx + b * HXST + k4 * 4) =
                xs[((size_t)(b0 + b) * TT + 0) * (II / 4) + k4];
        }
        float4 z = make_float4(0.f, 0.f, 0.f, 0.f);
        #pragma unroll
        for (int it = 0; it < (UB * HH / 4) / NTHR; it++) {
            int idx = tid + it * NTHR;
            int b = idx >> 7, k4 = idx & 127;
            *(float4*)(hx + b * HXST + II + k4 * 4) = z;
        }
    }
    const float bias0 = b_ih[0 * HH + j] + b_hh[0 * HH + j];
    const float bias1 = b_ih[1 * HH + j] + b_hh[1 * HH + j];
    const float bias2 = b_ih[2 * HH + j] + b_hh[2 * HH + j];
    const float bias3 = b_ih[3 * HH + j] + b_hh[3 * HH + j];
    const float bfj = bf[j];

    __syncthreads();

    // phase-1 pointers: this thread's k-quarter
    const ull* wiR  = (const ull*)(Wsm + (0 * 16 + u) * WST) + ks * KQ80;
    const ull* wfR  = (const ull*)(Wsm + (1 * 16 + u) * WST) + ks * KQ80;
    const ull* wgR  = (const ull*)(Wsm + (2 * 16 + u) * WST) + ks * KQ80;
    const ull* woR  = (const ull*)(Wsm + (3 * 16 + u) * WST) + ks * KQ80;
    const ull* hloR = (const ull*)(hx + blo * HXST) + ks * KQ80;
    const ull* hhiR = (const ull*)(hx + bhi * HXST) + ks * KQ80;
    // fe pointers: this thread's k-quarter of h (128 floats), rows now 16B-aligned
    const float4*     wfq  = (const float4*)(Wf + (size_t)j * HH + ks * 128);
    const ulonglong2* hloF = (const ulonglong2*)(hx + blo * HXST + II + ks * 128);
    const ulonglong2* hhiF = (const ulonglong2*)(hx + bhi * HXST + II + ks * 128);

    float* myred  = red + ((ks - 1) * 128 + bp * 16 + u) * REDST;   // valid when ks>=1
    float* myredf = redfe + ((ks - 1) * 128 + bp * 16 + u) * 2;
    const int prow = bp * 16 + u;
    unsigned* mybar = &g_bar[bg * 32];

    float c_lo = 0.f, c_hi = 0.f, h_lo = 0.f, h_hi = 0.f;   // live in ks==0 threads

    #pragma unroll 1
    for (int t = 0; t < TT; t++) {
        // ===== phase 1: 4 gates x 2 batches over this thread's k-quarter =====
        ull ai0 = 0, af0 = 0, ag0 = 0, ao0 = 0;
        ull ai1 = 0, af1 = 0, ag1 = 0, ao1 = 0;
        #pragma unroll 4
        for (int kk = 0; kk < KQ80; kk++) {
            ull v0 = hloR[kk];
            ull v1 = hhiR[kk];
            ull w0 = wiR[kk], w1 = wfR[kk], w2 = wgR[kk], w3 = woR[kk];
            ai0 = ffma2(w0, v0, ai0);  ai1 = ffma2(w0, v1, ai1);
            af0 = ffma2(w1, v0, af0);  af1 = ffma2(w1, v1, af1);
            ag0 = ffma2(w2, v0, ag0);  ag1 = ffma2(w2, v1, ag1);
            ao0 = ffma2(w3, v0, ao0);  ao1 = ffma2(w3, v1, ao1);
        }
        if (ks) {                                 // publish partials (scalar, stride 9)
            myred[0] = red2(ai0); myred[1] = red2(af0);
            myred[2] = red2(ag0); myred[3] = red2(ao0);
            myred[4] = red2(ai1); myred[5] = red2(af1);
            myred[6] = red2(ag1); myred[7] = red2(ao1);
        }
        __syncthreads();                          // S1

        const int p1 = (t + 1) & 1;
        if (!ks) {                                // owners: gather + activation
            const float* r0 = red + prow * REDST;
            const float* r1 = r0 + 128 * REDST;
            const float* r2 = r1 + 128 * REDST;
            float gi = red2(ai0) + r0[0] + r1[0] + r2[0] + bias0;
            float gf = red2(af0) + r0[1] + r1[1] + r2[1] + bias1;
            float gg = red2(ag0) + r0[2] + r1[2] + r2[2] + bias2;
            float go = red2(ao0) + r0[3] + r1[3] + r2[3] + bias3;
            float iv = sigm(gi), fv = sigm(gf), gv = tanhf(gg), ov = sigm(go);
            c_lo = fv * c_lo + iv * gv;
            h_lo = ov * tanhf(c_lo);
            gi = red2(ai1) + r0[4] + r1[4] + r2[4] + bias0;
            gf = red2(af1) + r0[5] + r1[5] + r2[5] + bias1;
            gg = red2(ag1) + r0[6] + r1[6] + r2[6] + bias2;
            go = red2(ao1) + r0[7] + r1[7] + r2[7] + bias3;
            iv = sigm(gi); fv = sigm(gf); gv = tanhf(gg); ov = sigm(go);
            c_hi = fv * c_hi + iv * gv;
            h_hi = ov * tanhf(c_hi);

            out[((size_t)gblo * TT + t) * HH + j] = h_lo;
            out[((size_t)gbhi * TT + t) * HH + j] = h_hi;
            __stcg(&g_Hbuf[p1][gblo * HH + j], h_lo);
            __stcg(&g_Hbuf[p1][gbhi * HH + j], h_hi);
        }

        // prefetch x_{t+1} (independent of barrier; phase-1 reads finished at S1)
        if (t + 1 < TT) {
            const float4* xs = (const float4*)x;
            int b = tid >> 5, k4 = tid & 31;      // 512 threads cover UB*II/4
            *(float4*)(hx + b * HXST + k4 * 4) =
                xs[((size_t)(b0 + b) * TT + (t + 1)) * (II / 4) + k4];
        }
        __syncthreads();                          // S2: all h stores issued CTA-wide

        // ===== per-batch-group grid barrier (32 CTAs) =====
        if (tid == 0) {
            __threadfence();                      // release h writes
            atomicAdd(mybar, 1u);
            const unsigned target = (unsigned)(t + 1) * GH;
            while (ld_acq(mybar) < target) { }
        }
        __syncthreads();                          // S3

        // ===== stage h_{t+1} into SMEM (vectorized) =====
        {
            const float4* hb = (const float4*)g_Hbuf[p1];
            #pragma unroll
            for (int it = 0; it < (UB * HH / 4) / NTHR; it++) {
                int idx = tid + it * NTHR;
                int b = idx >> 7, k4 = idx & 127;
                float4 v = __ldcg(&hb[(size_t)(b0 + b) * (HH / 4) + k4]);
                *(float4*)(hx + b * HXST + II + k4 * 4) = v;
            }
        }
        __syncthreads();                          // S4

        // ===== fe = exp(h_new @ Wf^T + bf); c *= fe  (k-split 4 ways) =====
        {
            ull s0 = 0, s1 = 0;                   // lo batch, hi batch
            #pragma unroll 4
            for (int qk = 0; qk < 32; qk++) {     // 32 x 4 floats = 128 k per quarter
                float4 w = __ldg(&wfq[qk]);
                ull w01 = pack2(w.x, w.y), w23 = pack2(w.z, w.w);
                ulonglong2 hl = hloF[qk];
                ulonglong2 hh = hhiF[qk];
                s0 = ffma2(w01, hl.x, s0); s0 = ffma2(w23, hl.y, s0);
                s1 = ffma2(w01, hh.x, s1); s1 = ffma2(w23, hh.y, s1);
            }
            if (ks) { myredf[0] = red2(s0); myredf[1] = red2(s1); }
            __syncthreads();                      // S5
            if (!ks) {
                const float* f0 = redfe + prow * 2;
                const float* f1 = f0 + 128 * 2;
                const float* f2 = f1 + 128 * 2;
                c_lo *= expf(red2(s0) + f0[0] + f1[0] + f2[0] + bfj);
                c_hi *= expf(red2(s1) + f0[1] + f1[1] + f2[1] + bfj);
            }
        }
    }

    // ===== final h, c (tuple flatten: out | h | c) =====
    if (!ks && out_elems >= (long long)BB * TT * HH + 2LL * BB * HH) {
        float* hout = out + (size_t)BB * TT * HH;
        float* cout = hout + (size_t)BB * HH;
        hout[gblo * HH + j] = h_lo;
        hout[gbhi * HH + j] = h_hi;
        cout[gblo * HH + j] = c_lo;
        cout[gbhi * HH + j] = c_hi;
    }
}

extern "C" void kernel_launch(void* const* d_in, const int* in_sizes, int n_in,
                              void* d_out, int out_size) {
    const float* x    = (const float*)d_in[0];
    const float* W_ih = (const float*)d_in[1];
    const float* W_hh = (const float*)d_in[2];
    const float* b_ih = (const float*)d_in[3];
    const float* b_hh = (const float*)d_in[4];
    const float* Wf   = (const float*)d_in[5];
    const float* bf   = (const float*)d_in[6];
    // d_in[7] = Wi, d_in[8] = bi: unused by the reference recurrence
    float* out = (float*)d_out;

    const size_t smem_bytes =
        (size_t)(64 * WST + UB * HXST + 3 * 128 * REDST + 3 * 128 * 2) * sizeof(float);
    // = (41088 + 10240 + 3456 + 768) * 4 = 222,208 B
    cudaFuncSetAttribute(sLSTM_70772471103948_kernel,
                         cudaFuncAttributeMaxDynamicSharedMemorySize, (int)smem_bytes);

    slstm_init_kernel<<<1, 32>>>();
    sLSTM_70772471103948_kernel<<<NCTA, NTHR, smem_bytes>>>(
        x, W_ih, W_hh, b_ih, b_hh, Wf, bf, out, (long long)out_size);
}

// round 12
// speedup vs baseline: 1.4264x; 1.0080x over previous
#include <cuda_runtime.h>
#include <cstddef>

// ---------------- problem constants ----------------
#define BB   64
#define TT   1024
#define II   128
#define HH   512
#define KK   640            // I + H

// ---------------- partitioning ----------------
#define GH   32             // hidden groups
#define GB   4              // batch groups
#define NCTA (GH*GB)        // 128 CTAs, one per SM, all resident
#define UH   16             // hidden units per CTA
#define UB   16             // batches per CTA
#define NTHR 512            // 16 u x 8 bp x 4 ks  (16 warps, 4/SMSP)

#define WST  642            // weight row stride: 642%32==2 -> u-lanes cover all 32 banks
#define HXST 644            // hx row stride: 644%32==4 (adjacent rows on different banks) AND 16B-aligned
#define REDST 11            // partial row stride: 10 data (8 gate + 2 fe) + 1; 11 coprime 32 -> conflict-free
#define KQ80 80             // ull (f32x2) elements per gate k-quarter: 640/2/4

typedef unsigned long long ull;

// persistent state (no cudaMalloc allowed)
__device__ float    g_Hbuf[2][BB*HH];
__device__ unsigned g_bar[GB * 32];   // one counter per batch group, separate lines

// ---------------- packed fp32x2 helpers (Blackwell) ----------------
__device__ __forceinline__ ull ffma2(ull a, ull b, ull c) {
    ull d;
    asm("fma.rn.f32x2 %0, %1, %2, %3;" : "=l"(d) : "l"(a), "l"(b), "l"(c));
    return d;
}
__device__ __forceinline__ ull pack2(float lo, float hi) {
    ull d; asm("mov.b64 %0, {%1, %2};" : "=l"(d) : "f"(lo), "f"(hi)); return d;
}
__device__ __forceinline__ float red2(ull v) {
    return __uint_as_float((unsigned)v) + __uint_as_float((unsigned)(v >> 32));
}
__device__ __forceinline__ float sigm(float x) { return 1.0f / (1.0f + expf(-x)); }

__device__ __forceinline__ unsigned ld_acq(const unsigned* p) {
    unsigned v;
    asm volatile("ld.acquire.gpu.global.u32 %0, [%1];" : "=r"(v) : "l"(p) : "memory");
    return v;
}

__global__ void slstm_init_kernel() {
    if (threadIdx.x < GB) g_bar[threadIdx.x * 32] = 0u;
}

// ---------------- persistent sLSTM kernel ----------------
extern "C" __global__ void __launch_bounds__(NTHR, 1)
sLSTM_70772471103948_kernel(const float* __restrict__ x,     // [B,T,I]
                            const float* __restrict__ W_ih,  // [4H,I]
                            const float* __restrict__ W_hh,  // [4H,H]
                            const float* __restrict__ b_ih,  // [4H]
                            const float* __restrict__ b_hh,  // [4H]
                            const float* __restrict__ Wf,    // [H,H]
                            const float* __restrict__ bf,    // [H]
                            float* __restrict__ out,         // [B,T,H] | h[B,H] | c[B,H]
                            long long out_elems)
{
    extern __shared__ float smem[];
    float* Wsm = smem;                           // 64 rows x WST
    float* hx  = smem + 64 * WST;                // 16 batch rows x HXST ([x_t | h_t])
    float* red = hx + UB * HXST;                 // 3*128 rows x REDST (ks=1..3 partials)

    const int tid = threadIdx.x;
    const int u   = tid & 15;                    // local hidden unit
    const int bp  = (tid >> 4) & 7;              // batch pair 0..7
    const int ks  = tid >> 7;                    // k quarter 0..3 (uniform per warp)
    const int hg  = blockIdx.x & (GH - 1);
    const int bg  = blockIdx.x >> 5;
    const int j0  = hg * UH;
    const int b0  = bg * UB;
    const int j   = j0 + u;                      // global hidden index
    const int blo = bp, bhi = bp + 8;
    const int gblo = b0 + blo, gbhi = b0 + bhi;

    // ---- stage gate weights into SMEM once ----
    for (int idx = tid; idx < 64 * KK; idx += NTHR) {
        int r  = idx / KK;
        int k  = idx - r * KK;
        int gg = r >> 4, uu = r & 15;
        int grow = gg * HH + j0 + uu;            // gate order: i,f,g,o
        float w = (k < II) ? W_ih[grow * II + k] : W_hh[grow * HH + (k - II)];
        Wsm[r * WST + k] = w;
    }
    // ---- stage x_0 ; h_0 = 0 ----
    {
        const float4* xs = (const float4*)x;
        {
            int b = tid >> 5, k4 = tid & 31;      // UB*II/4 = 512 = NTHR
            *(float4*)(hx + b * HXST + k4 * 4) =
                xs[((size_t)(b0 + b) * TT + 0) * (II / 4) + k4];
        }
        float4 z = make_float4(0.f, 0.f, 0.f, 0.f);
        #pragma unroll
        for (int it = 0; it < (UB * HH / 4) / NTHR; it++) {
            int idx = tid + it * NTHR;
            int b = idx >> 7, k4 = idx & 127;
            *(float4*)(hx + b * HXST + II + k4 * 4) = z;
        }
    }
    const float bias0 = b_ih[0 * HH + j] + b_hh[0 * HH + j];
    const float bias1 = b_ih[1 * HH + j] + b_hh[1 * HH + j];
    const float bias2 = b_ih[2 * HH + j] + b_hh[2 * HH + j];
    const float bias3 = b_ih[3 * HH + j] + b_hh[3 * HH + j];
    const float bfj = bf[j];

    __syncthreads();

    // phase-1 pointers: this thread's gate k-quarter
    const ull* wiR  = (const ull*)(Wsm + (0 * 16 + u) * WST) + ks * KQ80;
    const ull* wfR  = (const ull*)(Wsm + (1 * 16 + u) * WST) + ks * KQ80;
    const ull* wgR  = (const ull*)(Wsm + (2 * 16 + u) * WST) + ks * KQ80;
    const ull* woR  = (const ull*)(Wsm + (3 * 16 + u) * WST) + ks * KQ80;
    const ull* hloR = (const ull*)(hx + blo * HXST) + ks * KQ80;
    const ull* hhiR = (const ull*)(hx + bhi * HXST) + ks * KQ80;
    // fe pointers: this thread's h k-quarter (128 floats of h), rows 16B-aligned
    const float4*     wfq  = (const float4*)(Wf + (size_t)j * HH + ks * 128);
    const ulonglong2* hloF = (const ulonglong2*)(hx + blo * HXST + II + ks * 128);
    const ulonglong2* hhiF = (const ulonglong2*)(hx + bhi * HXST + II + ks * 128);

    float* myred = red + ((ks - 1) * 128 + bp * 16 + u) * REDST;   // valid when ks>=1
    const int prow = bp * 16 + u;
    unsigned* mybar = &g_bar[bg * 32];

    // owned (j, gblo)/(j, gbhi) state; c held RAW (pending fe of previous h)
    float c_lo = 0.f, c_hi = 0.f, h_lo = 0.f, h_hi = 0.f;

    #pragma unroll 1
    for (int t = 0; t < TT; t++) {
        // ===== phase 1a: gates(t) from h_{t-1}, this thread's k-quarter =====
        ull ai0 = 0, af0 = 0, ag0 = 0, ao0 = 0;
        ull ai1 = 0, af1 = 0, ag1 = 0, ao1 = 0;
        #pragma unroll 4
        for (int kk = 0; kk < KQ80; kk++) {
            ull v0 = hloR[kk];
            ull v1 = hhiR[kk];
            ull w0 = wiR[kk], w1 = wfR[kk], w2 = wgR[kk], w3 = woR[kk];
            ai0 = ffma2(w0, v0, ai0);  ai1 = ffma2(w0, v1, ai1);
            af0 = ffma2(w1, v0, af0);  af1 = ffma2(w1, v1, af1);
            ag0 = ffma2(w2, v0, ag0);  ag1 = ffma2(w2, v1, ag1);
            ao0 = ffma2(w3, v0, ao0);  ao1 = ffma2(w3, v1, ao1);
        }
        // ===== phase 1b: fe(h_{t-1}) partials over this thread's h-quarter =====
        ull s0 = 0, s1 = 0;
        #pragma unroll 4
        for (int qk = 0; qk < 32; qk++) {         // 32 x 4 floats = 128 h-k per quarter
            float4 w = __ldg(&wfq[qk]);
            ull w01 = pack2(w.x, w.y), w23 = pack2(w.z, w.w);
            ulonglong2 hl = hloF[qk];
            ulonglong2 hh = hhiF[qk];
            s0 = ffma2(w01, hl.x, s0); s0 = ffma2(w23, hl.y, s0);
            s1 = ffma2(w01, hh.x, s1); s1 = ffma2(w23, hh.y, s1);
        }
        if (ks) {                                 // publish 10 partials (stride 11)
            myred[0] = red2(ai0); myred[1] = red2(af0);
            myred[2] = red2(ag0); myred[3] = red2(ao0);
            myred[4] = red2(ai1); myred[5] = red2(af1);
            myred[6] = red2(ag1); myred[7] = red2(ao1);
            myred[8] = red2(s0);  myred[9] = red2(s1);
        }
        __syncthreads();                          // S1

        const int p1 = (t + 1) & 1;
        if (!ks) {                                // owners: gather + deferred fe + activation
            const float* r0 = red + prow * REDST;
            const float* r1 = r0 + 128 * REDST;
            const float* r2 = r1 + 128 * REDST;
            // deferred forget-exp of previous step (t=0: h=0 -> fe*0 harmless)
            float felo = expf(red2(s0) + r0[8] + r1[8] + r2[8] + bfj);
            float fehi = expf(red2(s1) + r0[9] + r1[9] + r2[9] + bfj);
            c_lo *= felo;
            c_hi *= fehi;

            float gi = red2(ai0) + r0[0] + r1[0] + r2[0] + bias0;
            float gf = red2(af0) + r0[1] + r1[1] + r2[1] + bias1;
            float gg = red2(ag0) + r0[2] + r1[2] + r2[2] + bias2;
            float go = red2(ao0) + r0[3] + r1[3] + r2[3] + bias3;
            float iv = sigm(gi), fv = sigm(gf), gv = tanhf(gg), ov = sigm(go);
            c_lo = fv * c_lo + iv * gv;
            h_lo = ov * tanhf(c_lo);
            gi = red2(ai1) + r0[4] + r1[4] + r2[4] + bias0;
            gf = red2(af1) + r0[5] + r1[5] + r2[5] + bias1;
            gg = red2(ag1) + r0[6] + r1[6] + r2[6] + bias2;
            go = red2(ao1) + r0[7] + r1[7] + r2[7] + bias3;
            iv = sigm(gi); fv = sigm(gf); gv = tanhf(gg); ov = sigm(go);
            c_hi = fv * c_hi + iv * gv;
            h_hi = ov * tanhf(c_hi);

            out[((size_t)gblo * TT + t) * HH + j] = h_lo;
            out[((size_t)gbhi * TT + t) * HH + j] = h_hi;
            __stcg(&g_Hbuf[p1][gblo * HH + j], h_lo);
            __stcg(&g_Hbuf[p1][gbhi * HH + j], h_hi);
        }

        // prefetch x_{t+1} (hx.x reads finished at S1)
        if (t + 1 < TT) {
            const float4* xs = (const float4*)x;
            int b = tid >> 5, k4 = tid & 31;      // 512 threads cover UB*II/4
            *(float4*)(hx + b * HXST + k4 * 4) =
                xs[((size_t)(b0 + b) * TT + (t + 1)) * (II / 4) + k4];
        }
        __syncthreads();                          // S2: all h stores issued CTA-wide

        // ===== per-batch-group grid barrier (32 CTAs) =====
        if (tid == 0) {
            __threadfence();                      // release h writes
            atomicAdd(mybar, 1u);
            const unsigned target = (unsigned)(t + 1) * GH;
            while (ld_acq(mybar) < target) { }
        }
        __syncthreads();                          // S3

        // ===== stage h_t into SMEM (vectorized) =====
        {
            const float4* hb = (const float4*)g_Hbuf[p1];
            #pragma unroll
            for (int it = 0; it < (UB * HH / 4) / NTHR; it++) {
                int idx = tid + it * NTHR;
                int b = idx >> 7, k4 = idx & 127;
                float4 v = __ldcg(&hb[(size_t)(b0 + b) * (HH / 4) + k4]);
                *(float4*)(hx + b * HXST + II + k4 * 4) = v;
            }
        }
        __syncthreads();                          // S4
    }

    // ===== epilogue: apply final fe(h_{T-1}) to raw c =====
    {
        ull s0 = 0, s1 = 0;
        #pragma unroll 4
        for (int qk = 0; qk < 32; qk++) {
            float4 w = __ldg(&wfq[qk]);
            ull w01 = pack2(w.x, w.y), w23 = pack2(w.z, w.w);
            ulonglong2 hl = hloF[qk];
            ulonglong2 hh = hhiF[qk];
            s0 = ffma2(w01, hl.x, s0); s0 = ffma2(w23, hl.y, s0);
            s1 = ffma2(w01, hh.x, s1); s1 = ffma2(w23, hh.y, s1);
        }
        if (ks) { myred[8] = red2(s0); myred[9] = red2(s1); }
        __syncthreads();
        if (!ks) {
            const float* r0 = red + prow * REDST;
            const float* r1 = r0 + 128 * REDST;
            const float* r2 = r1 + 128 * REDST;
            c_lo *= expf(red2(s0) + r0[8] + r1[8] + r2[8] + bfj);
            c_hi *= expf(red2(s1) + r0[9] + r1[9] + r2[9] + bfj);
        }
    }

    // ===== final h, c (tuple flatten: out | h | c) =====
    if (!ks && out_elems >= (long long)BB * TT * HH + 2LL * BB * HH) {
        float* hout = out + (size_t)BB * TT * HH;
        float* cout = hout + (size_t)BB * HH;
        hout[gblo * HH + j] = h_lo;
        hout[gbhi * HH + j] = h_hi;
        cout[gblo * HH + j] = c_lo;
        cout[gbhi * HH + j] = c_hi;
    }
}

extern "C" void kernel_launch(void* const* d_in, const int* in_sizes, int n_in,
                              void* d_out, int out_size) {
    const float* x    = (const float*)d_in[0];
    const float* W_ih = (const float*)d_in[1];
    const float* W_hh = (const float*)d_in[2];
    const float* b_ih = (const float*)d_in[3];
    const float* b_hh = (const float*)d_in[4];
    const float* Wf   = (const float*)d_in[5];
    const float* bf   = (const float*)d_in[6];
    // d_in[7] = Wi, d_in[8] = bi: unused by the reference recurrence
    float* out = (float*)d_out;

    const size_t smem_bytes =
        (size_t)(64 * WST + UB * HXST + 3 * 128 * REDST) * sizeof(float);
    // = (41088 + 10304 + 4224) * 4 = 222,464 B
    cudaFuncSetAttribute(sLSTM_70772471103948_kernel,
                         cudaFuncAttributeMaxDynamicSharedMemorySize, (int)smem_bytes);

    slstm_init_kernel<<<1, 32>>>();
    sLSTM_70772471103948_kernel<<<NCTA, NTHR, smem_bytes>>>(
        x, W_ih, W_hh, b_ih, b_hh, Wf, bf, out, (long long)out_size);
}

// round 13
// speedup vs baseline: 1.4503x; 1.0167x over previous
#include <cuda_runtime.h>
#include <cstddef>

// ---------------- problem constants ----------------
#define BB   64
#define TT   1024
#define II   128
#define HH   512
#define KK   640            // I + H

// ---------------- partitioning ----------------
#define GH   32             // hidden groups
#define GB   4              // batch groups
#define NCTA (GH*GB)        // 128 CTAs, one per SM, all resident
#define UH   16             // hidden units per CTA
#define UB   16             // batches per CTA
#define NTHR 512            // 16 u x 8 bp x 4 ks  (16 warps, 4/SMSP)

#define WST  642            // weight row stride: 642%32==2 -> u-lanes cover all 32 banks
#define HXST 644            // hx row stride: 644%32==4 AND 16B-aligned
#define REDST 11            // partial row stride (10 data + 1), 11 coprime 32
#define RED4ST 7            // ks0 hi-partial row stride (5 data + 2), 7 coprime 32
#define KQ80 80             // ull (f32x2) elements per gate k-quarter: 640/2/4

typedef unsigned long long ull;

// persistent state (no cudaMalloc allowed)
__device__ float    g_Hbuf[2][BB*HH];
__device__ unsigned g_bar[GB * 32];   // one counter per batch group, separate lines

// ---------------- packed fp32x2 + fast-activation helpers ----------------
__device__ __forceinline__ ull ffma2(ull a, ull b, ull c) {
    ull d;
    asm("fma.rn.f32x2 %0, %1, %2, %3;" : "=l"(d) : "l"(a), "l"(b), "l"(c));
    return d;
}
__device__ __forceinline__ ull pack2(float lo, float hi) {
    ull d; asm("mov.b64 %0, {%1, %2};" : "=l"(d) : "f"(lo), "f"(hi)); return d;
}
__device__ __forceinline__ float red2(ull v) {
    return __uint_as_float((unsigned)v) + __uint_as_float((unsigned)(v >> 32));
}
__device__ __forceinline__ float tanha(float x) {
    float y; asm("tanh.approx.f32 %0, %1;" : "=f"(y) : "f"(x)); return y;
}
__device__ __forceinline__ float sigm(float x) {          // 1 MUFU sigmoid
    return fmaf(tanha(0.5f * x), 0.5f, 0.5f);
}
__device__ __forceinline__ unsigned ld_acq(const unsigned* p) {
    unsigned v;
    asm volatile("ld.acquire.gpu.global.u32 %0, [%1];" : "=r"(v) : "l"(p) : "memory");
    return v;
}

__global__ void slstm_init_kernel() {
    if (threadIdx.x < GB) g_bar[threadIdx.x * 32] = 0u;
}

// ---------------- persistent sLSTM kernel ----------------
extern "C" __global__ void __launch_bounds__(NTHR, 1)
sLSTM_70772471103948_kernel(const float* __restrict__ x,     // [B,T,I]
                            const float* __restrict__ W_ih,  // [4H,I]
                            const float* __restrict__ W_hh,  // [4H,H]
                            const float* __restrict__ b_ih,  // [4H]
                            const float* __restrict__ b_hh,  // [4H]
                            const float* __restrict__ Wf,    // [H,H]
                            const float* __restrict__ bf,    // [H]
                            float* __restrict__ out,         // [B,T,H] | h[B,H] | c[B,H]
                            long long out_elems)
{
    extern __shared__ float smem[];
    float* Wsm  = smem;                          // 64 rows x WST
    float* hx   = smem + 64 * WST;               // 16 batch rows x HXST ([x_t | h_t])
    float* red  = hx + UB * HXST;                // 3*128 rows x REDST (ks=1..3 partials)
    float* red4 = red + 3 * 128 * REDST;         // 128 rows x RED4ST (ks=0 hi partials)

    const int tid = threadIdx.x;
    const int u   = tid & 15;                    // local hidden unit
    const int bp  = (tid >> 4) & 7;              // batch pair 0..7
    const int ks  = tid >> 7;                    // k quarter 0..3 (uniform per warp)
    const int hg  = blockIdx.x & (GH - 1);
    const int bg  = blockIdx.x >> 5;
    const int j0  = hg * UH;
    const int b0  = bg * UB;
    const int j   = j0 + u;                      // global hidden index
    const int blo = bp, bhi = bp + 8;
    const int gblo = b0 + blo, gbhi = b0 + bhi;

    // ---- stage gate weights into SMEM once ----
    for (int idx = tid; idx < 64 * KK; idx += NTHR) {
        int r  = idx / KK;
        int k  = idx - r * KK;
        int gg = r >> 4, uu = r & 15;
        int grow = gg * HH + j0 + uu;            // gate order: i,f,g,o
        float w = (k < II) ? W_ih[grow * II + k] : W_hh[grow * HH + (k - II)];
        Wsm[r * WST + k] = w;
    }
    // ---- stage x_0 ; h_0 = 0 ----
    {
        const float4* xs = (const float4*)x;
        {
            int b = tid >> 5, k4 = tid & 31;      // UB*II/4 = 512 = NTHR
            *(float4*)(hx + b * HXST + k4 * 4) =
                xs[((size_t)(b0 + b) * TT + 0) * (II / 4) + k4];
        }
        float4 z = make_float4(0.f, 0.f, 0.f, 0.f);
        #pragma unroll
        for (int it = 0; it < (UB * HH / 4) / NTHR; it++) {
            int idx = tid + it * NTHR;
            int b = idx >> 7, k4 = idx & 127;
            *(float4*)(hx + b * HXST + II + k4 * 4) = z;
        }
    }
    const float bias0 = b_ih[0 * HH + j] + b_hh[0 * HH + j];
    const float bias1 = b_ih[1 * HH + j] + b_hh[1 * HH + j];
    const float bias2 = b_ih[2 * HH + j] + b_hh[2 * HH + j];
    const float bias3 = b_ih[3 * HH + j] + b_hh[3 * HH + j];
    const float bfj = bf[j];

    __syncthreads();

    // phase-1 pointers: this thread's gate k-quarter
    const ull* wiR  = (const ull*)(Wsm + (0 * 16 + u) * WST) + ks * KQ80;
    const ull* wfR  = (const ull*)(Wsm + (1 * 16 + u) * WST) + ks * KQ80;
    const ull* wgR  = (const ull*)(Wsm + (2 * 16 + u) * WST) + ks * KQ80;
    const ull* woR  = (const ull*)(Wsm + (3 * 16 + u) * WST) + ks * KQ80;
    const ull* hloR = (const ull*)(hx + blo * HXST) + ks * KQ80;
    const ull* hhiR = (const ull*)(hx + bhi * HXST) + ks * KQ80;
    // fe pointers: this thread's h k-quarter (128 floats of h)
    const float4*     wfq  = (const float4*)(Wf + (size_t)j * HH + ks * 128);
    const ulonglong2* hloF = (const ulonglong2*)(hx + blo * HXST + II + ks * 128);
    const ulonglong2* hhiF = (const ulonglong2*)(hx + bhi * HXST + II + ks * 128);

    const int prow = bp * 16 + u;
    float* myred = red + ((ks - 1) * 128 + prow) * REDST;   // valid when ks>=1
    float* myred4 = red4 + prow * RED4ST;                   // used by ks==0
    unsigned* mybar = &g_bar[bg * 32];

    // state: (j,gblo) lives in ks==0 threads; (j,gbhi) lives in ks==1 threads.
    // c held RAW (pending fe of previous h)
    float c_lo = 0.f, c_hi = 0.f, h_lo = 0.f, h_hi = 0.f;

    #pragma unroll 1
    for (int t = 0; t < TT; t++) {
        // ===== phase 1a: gates(t) from h_{t-1}, this thread's k-quarter =====
        ull ai0 = 0, af0 = 0, ag0 = 0, ao0 = 0;
        ull ai1 = 0, af1 = 0, ag1 = 0, ao1 = 0;
        #pragma unroll 4
        for (int kk = 0; kk < KQ80; kk++) {
            ull v0 = hloR[kk];
            ull v1 = hhiR[kk];
            ull w0 = wiR[kk], w1 = wfR[kk], w2 = wgR[kk], w3 = woR[kk];
            ai0 = ffma2(w0, v0, ai0);  ai1 = ffma2(w0, v1, ai1);
            af0 = ffma2(w1, v0, af0);  af1 = ffma2(w1, v1, af1);
            ag0 = ffma2(w2, v0, ag0);  ag1 = ffma2(w2, v1, ag1);
            ao0 = ffma2(w3, v0, ao0);  ao1 = ffma2(w3, v1, ao1);
        }
        // ===== phase 1b: fe(h_{t-1}) partials over this thread's h-quarter =====
        ull s0 = 0, s1 = 0;
        #pragma unroll 4
        for (int qk = 0; qk < 32; qk++) {         // 32 x 4 floats = 128 h-k per quarter
            float4 w = __ldg(&wfq[qk]);
            ull w01 = pack2(w.x, w.y), w23 = pack2(w.z, w.w);
            ulonglong2 hl = hloF[qk];
            ulonglong2 hh = hhiF[qk];
            s0 = ffma2(w01, hl.x, s0); s0 = ffma2(w23, hl.y, s0);
            s1 = ffma2(w01, hh.x, s1); s1 = ffma2(w23, hh.y, s1);
        }
        if (ks) {                                 // publish 10 partials (stride 11)
            myred[0] = red2(ai0); myred[1] = red2(af0);
            myred[2] = red2(ag0); myred[3] = red2(ao0);
            myred[4] = red2(ai1); myred[5] = red2(af1);
            myred[6] = red2(ag1); myred[7] = red2(ao1);
            myred[8] = red2(s0);  myred[9] = red2(s1);
        } else {                                  // ks0 publishes its HI partials
            myred4[0] = red2(ai1); myred4[1] = red2(af1);
            myred4[2] = red2(ag1); myred4[3] = red2(ao1);
            myred4[4] = red2(s1);
        }
        __syncthreads();                          // S1

        const int p1 = (t + 1) & 1;
        if (ks == 0) {                            // owner of LO element (u, gblo)
            const float* r1 = red + prow * REDST;
            const float* r2 = r1 + 128 * REDST;
            const float* r3 = r2 + 128 * REDST;
            float fe = __expf(red2(s0) + r1[8] + r2[8] + r3[8] + bfj);
            float cr = c_lo * fe;                 // deferred fe of previous step
            float gi = red2(ai0) + r1[0] + r2[0] + r3[0] + bias0;
            float gf = red2(af0) + r1[1] + r2[1] + r3[1] + bias1;
            float gg = red2(ag0) + r1[2] + r2[2] + r3[2] + bias2;
            float go = red2(ao0) + r1[3] + r2[3] + r3[3] + bias3;
            float iv = sigm(gi), fv = sigm(gf), gv = tanha(gg), ov = sigm(go);
            c_lo = fv * cr + iv * gv;
            h_lo = ov * tanha(c_lo);
            out[((size_t)gblo * TT + t) * HH + j] = h_lo;
            __stcg(&g_Hbuf[p1][gblo * HH + j], h_lo);
        } else if (ks == 1) {                     // owner of HI element (u, gbhi)
            const float* r2 = red + (128 + prow) * REDST;   // ks=2
            const float* r3 = r2 + 128 * REDST;             // ks=3
            const float* r0 = red4 + prow * RED4ST;         // ks=0 hi
            float fe = __expf(red2(s1) + r0[4] + r2[9] + r3[9] + bfj);
            float cr = c_hi * fe;
            float gi = red2(ai1) + r0[0] + r2[4] + r3[4] + bias0;
            float gf = red2(af1) + r0[1] + r2[5] + r3[5] + bias1;
            float gg = red2(ag1) + r0[2] + r2[6] + r3[6] + bias2;
            float go = red2(ao1) + r0[3] + r2[7] + r3[7] + bias3;
            float iv = sigm(gi), fv = sigm(gf), gv = tanha(gg), ov = sigm(go);
            c_hi = fv * cr + iv * gv;
            h_hi = ov * tanha(c_hi);
            out[((size_t)gbhi * TT + t) * HH + j] = h_hi;
            __stcg(&g_Hbuf[p1][gbhi * HH + j], h_hi);
        }

        // prefetch x_{t+1} (hx.x reads finished at S1)
        if (t + 1 < TT) {
            const float4* xs = (const float4*)x;
            int b = tid >> 5, k4 = tid & 31;      // 512 threads cover UB*II/4
            *(float4*)(hx + b * HXST + k4 * 4) =
                xs[((size_t)(b0 + b) * TT + (t + 1)) * (II / 4) + k4];
        }
        __syncthreads();                          // S2: all h stores issued CTA-wide

        // ===== per-batch-group grid barrier (32 CTAs) =====
        if (tid == 0) {
            __threadfence();                      // release h writes
            atomicAdd(mybar, 1u);
            const unsigned target = (unsigned)(t + 1) * GH;
            while (ld_acq(mybar) < target) { }
        }
        __syncthreads();                          // S3

        // ===== stage h_t into SMEM (vectorized) =====
        {
            const float4* hb = (const float4*)g_Hbuf[p1];
            #pragma unroll
            for (int it = 0; it < (UB * HH / 4) / NTHR; it++) {
                int idx = tid + it * NTHR;
                int b = idx >> 7, k4 = idx & 127;
                float4 v = __ldcg(&hb[(size_t)(b0 + b) * (HH / 4) + k4]);
                *(float4*)(hx + b * HXST + II + k4 * 4) = v;
            }
        }
        __syncthreads();                          // S4
    }

    // ===== epilogue: apply final fe(h_{T-1}) to raw c =====
    {
        ull s0 = 0, s1 = 0;
        #pragma unroll 4
        for (int qk = 0; qk < 32; qk++) {
            float4 w = __ldg(&wfq[qk]);
            ull w01 = pack2(w.x, w.y), w23 = pack2(w.z, w.w);
            ulonglong2 hl = hloF[qk];
            ulonglong2 hh = hhiF[qk];
            s0 = ffma2(w01, hl.x, s0); s0 = ffma2(w23, hl.y, s0);
            s1 = ffma2(w01, hh.x, s1); s1 = ffma2(w23, hh.y, s1);
        }
        if (ks) { myred[8] = red2(s0); myred[9] = red2(s1); }
        else    { myred4[4] = red2(s1); }
        __syncthreads();
        if (ks == 0) {
            const float* r1 = red + prow * REDST;
            const float* r2 = r1 + 128 * REDST;
            const float* r3 = r2 + 128 * REDST;
            c_lo *= __expf(red2(s0) + r1[8] + r2[8] + r3[8] + bfj);
        } else if (ks == 1) {
            const float* r2 = red + (128 + prow) * REDST;
            const float* r3 = r2 + 128 * REDST;
            const float* r0 = red4 + prow * RED4ST;
            c_hi *= __expf(red2(s1) + r0[4] + r2[9] + r3[9] + bfj);
        }
    }

    // ===== final h, c (tuple flatten: out | h | c) =====
    if (out_elems >= (long long)BB * TT * HH + 2LL * BB * HH) {
        float* hout = out + (size_t)BB * TT * HH;
        float* cout = hout + (size_t)BB * HH;
        if (ks == 0) {
            hout[gblo * HH + j] = h_lo;
            cout[gblo * HH + j] = c_lo;
        } else if (ks == 1) {
            hout[gbhi * HH + j] = h_hi;
            cout[gbhi * HH + j] = c_hi;
        }
    }
}

extern "C" void kernel_launch(void* const* d_in, const int* in_sizes, int n_in,
                              void* d_out, int out_size) {
    const float* x    = (const float*)d_in[0];
    const float* W_ih = (const float*)d_in[1];
    const float* W_hh = (const float*)d_in[2];
    const float* b_ih = (const float*)d_in[3];
    const float* b_hh = (const float*)d_in[4];
    const float* Wf   = (const float*)d_in[5];
    const float* bf   = (const float*)d_in[6];
    // d_in[7] = Wi, d_in[8] = bi: unused by the reference recurrence
    float* out = (float*)d_out;

    const size_t smem_bytes =
        (size_t)(64 * WST + UB * HXST + 3 * 128 * REDST + 128 * RED4ST) * sizeof(float);
    // = (41088 + 10304 + 4224 + 896) * 4 = 226,048 B
    cudaFuncSetAttribute(sLSTM_70772471103948_kernel,
                         cudaFuncAttributeMaxDynamicSharedMemorySize, (int)smem_bytes);

    slstm_init_kernel<<<1, 32>>>();
    sLSTM_70772471103948_kernel<<<NCTA, NTHR, smem_bytes>>>(
        x, W_ih, W_hh, b_ih, b_hh, Wf, bf, out, (long long)out_size);
}

// round 14
// speedup vs baseline: 1.4520x; 1.0011x over previous
#include <cuda_runtime.h>
#include <cstddef>

// ---------------- problem constants ----------------
#define BB   64
#define TT   1024
#define II   128
#define HH   512
#define KK   640            // I + H

// ---------------- partitioning ----------------
#define GH   32             // hidden groups
#define GB   4              // batch groups
#define NCTA (GH*GB)        // 128 CTAs, one per SM, all resident
#define UH   16             // hidden units per CTA
#define UB   16             // batches per CTA
#define NTHR 512            // 16 u x 8 bp x 4 ks  (16 warps, 4/SMSP)

#define WST  642            // weight row stride: 642%32==2 -> u-lanes cover all 32 banks
#define HXST 644            // hx row stride: 644%32==4 AND 16B-aligned
#define REDST 11            // partial row stride (10 data + 1), 11 coprime 32
#define RED4ST 7            // ks0 hi-partial row stride (5 data + 2), 7 coprime 32
#define KQ80 80             // ull (f32x2) elements per gate k-quarter: 640/2/4

typedef unsigned long long ull;

// persistent state (no cudaMalloc allowed)
__device__ float    g_Hbuf[2][BB*HH];
__device__ unsigned g_bar[GB * 32];   // one counter per batch group, separate lines

// ---------------- packed fp32x2 + fast-activation helpers ----------------
__device__ __forceinline__ ull ffma2(ull a, ull b, ull c) {
    ull d;
    asm("fma.rn.f32x2 %0, %1, %2, %3;" : "=l"(d) : "l"(a), "l"(b), "l"(c));
    return d;
}
__device__ __forceinline__ ull pack2(float lo, float hi) {
    ull d; asm("mov.b64 %0, {%1, %2};" : "=l"(d) : "f"(lo), "f"(hi)); return d;
}
__device__ __forceinline__ float red2(ull v) {
    return __uint_as_float((unsigned)v) + __uint_as_float((unsigned)(v >> 32));
}
__device__ __forceinline__ float tanha(float x) {
    float y; asm("tanh.approx.f32 %0, %1;" : "=f"(y) : "f"(x)); return y;
}
__device__ __forceinline__ float sigm(float x) {          // 1 MUFU sigmoid
    return fmaf(tanha(0.5f * x), 0.5f, 0.5f);
}
__device__ __forceinline__ unsigned ld_acq(const unsigned* p) {
    unsigned v;
    asm volatile("ld.acquire.gpu.global.u32 %0, [%1];" : "=r"(v) : "l"(p) : "memory");
    return v;
}

__global__ void slstm_init_kernel() {
    if (threadIdx.x < GB) g_bar[threadIdx.x * 32] = 0u;
}

// ---------------- persistent sLSTM kernel ----------------
extern "C" __global__ void __launch_bounds__(NTHR, 1)
sLSTM_70772471103948_kernel(const float* __restrict__ x,     // [B,T,I]
                            const float* __restrict__ W_ih,  // [4H,I]
                            const float* __restrict__ W_hh,  // [4H,H]
                            const float* __restrict__ b_ih,  // [4H]
                            const float* __restrict__ b_hh,  // [4H]
                            const float* __restrict__ Wf,    // [H,H]
                            const float* __restrict__ bf,    // [H]
                            float* __restrict__ out,         // [B,T,H] | h[B,H] | c[B,H]
                            long long out_elems)
{
    extern __shared__ float smem[];
    float* Wsm  = smem;                          // 64 rows x WST
    float* hx   = smem + 64 * WST;               // 16 batch rows x HXST ([x_t | h_t])
    float* red  = hx + UB * HXST;                // 3*128 rows x REDST (ks=1..3 partials)
    float* red4 = red + 3 * 128 * REDST;         // 128 rows x RED4ST (ks=0 hi partials)

    const int tid = threadIdx.x;
    const int u   = tid & 15;                    // local hidden unit
    const int bp  = (tid >> 4) & 7;              // batch pair 0..7
    const int ks  = tid >> 7;                    // k quarter 0..3 (uniform per warp)
    const int hg  = blockIdx.x & (GH - 1);
    const int bg  = blockIdx.x >> 5;
    const int j0  = hg * UH;
    const int b0  = bg * UB;
    const int j   = j0 + u;                      // global hidden index
    const int blo = bp, bhi = bp + 8;
    const int gblo = b0 + blo, gbhi = b0 + bhi;

    // ---- stage gate weights into SMEM once ----
    for (int idx = tid; idx < 64 * KK; idx += NTHR) {
        int r  = idx / KK;
        int k  = idx - r * KK;
        int gg = r >> 4, uu = r & 15;
        int grow = gg * HH + j0 + uu;            // gate order: i,f,g,o
        float w = (k < II) ? W_ih[grow * II + k] : W_hh[grow * HH + (k - II)];
        Wsm[r * WST + k] = w;
    }
    // ---- stage x_0 ; h_0 = 0 ----
    {
        const float4* xs = (const float4*)x;
        {
            int b = tid >> 5, k4 = tid & 31;      // UB*II/4 = 512 = NTHR
            *(float4*)(hx + b * HXST + k4 * 4) =
                xs[((size_t)(b0 + b) * TT + 0) * (II / 4) + k4];
        }
        float4 z = make_float4(0.f, 0.f, 0.f, 0.f);
        #pragma unroll
        for (int it = 0; it < (UB * HH / 4) / NTHR; it++) {
            int idx = tid + it * NTHR;
            int b = idx >> 7, k4 = idx & 127;
            *(float4*)(hx + b * HXST + II + k4 * 4) = z;
        }
    }
    const float bias0 = b_ih[0 * HH + j] + b_hh[0 * HH + j];
    const float bias1 = b_ih[1 * HH + j] + b_hh[1 * HH + j];
    const float bias2 = b_ih[2 * HH + j] + b_hh[2 * HH + j];
    const float bias3 = b_ih[3 * HH + j] + b_hh[3 * HH + j];
    const float bfj = bf[j];

    __syncthreads();

    // phase-1 pointers: this thread's gate k-quarter
    const ull* wiR  = (const ull*)(Wsm + (0 * 16 + u) * WST) + ks * KQ80;
    const ull* wfR  = (const ull*)(Wsm + (1 * 16 + u) * WST) + ks * KQ80;
    const ull* wgR  = (const ull*)(Wsm + (2 * 16 + u) * WST) + ks * KQ80;
    const ull* woR  = (const ull*)(Wsm + (3 * 16 + u) * WST) + ks * KQ80;
    const ull* hloR = (const ull*)(hx + blo * HXST) + ks * KQ80;
    const ull* hhiR = (const ull*)(hx + bhi * HXST) + ks * KQ80;
    // fe pointers: this thread's h k-quarter (128 floats of h)
    const float4*     wfq  = (const float4*)(Wf + (size_t)j * HH + ks * 128);
    const ulonglong2* hloF = (const ulonglong2*)(hx + blo * HXST + II + ks * 128);
    const ulonglong2* hhiF = (const ulonglong2*)(hx + bhi * HXST + II + ks * 128);

    const int prow = bp * 16 + u;
    float* myred = red + ((ks - 1) * 128 + prow) * REDST;   // valid when ks>=1
    float* myred4 = red4 + prow * RED4ST;                   // used by ks==0
    unsigned* mybar = &g_bar[bg * 32];

    // state: (j,gblo) lives in ks==0 threads; (j,gbhi) lives in ks==1 threads.
    // c held RAW (pending fe of previous h)
    float c_lo = 0.f, c_hi = 0.f, h_lo = 0.f, h_hi = 0.f;

    #pragma unroll 1
    for (int t = 0; t < TT; t++) {
        // ===== phase 1a: gates(t) from h_{t-1}, this thread's k-quarter =====
        ull ai0 = 0, af0 = 0, ag0 = 0, ao0 = 0;
        ull ai1 = 0, af1 = 0, ag1 = 0, ao1 = 0;
        #pragma unroll 4
        for (int kk = 0; kk < KQ80; kk++) {
            ull v0 = hloR[kk];
            ull v1 = hhiR[kk];
            ull w0 = wiR[kk], w1 = wfR[kk], w2 = wgR[kk], w3 = woR[kk];
            ai0 = ffma2(w0, v0, ai0);  ai1 = ffma2(w0, v1, ai1);
            af0 = ffma2(w1, v0, af0);  af1 = ffma2(w1, v1, af1);
            ag0 = ffma2(w2, v0, ag0);  ag1 = ffma2(w2, v1, ag1);
            ao0 = ffma2(w3, v0, ao0);  ao1 = ffma2(w3, v1, ao1);
        }
        // ===== phase 1b: fe(h_{t-1}) partials over this thread's h-quarter =====
        ull s0 = 0, s1 = 0;
        #pragma unroll 4
        for (int qk = 0; qk < 32; qk++) {         // 32 x 4 floats = 128 h-k per quarter
            float4 w = __ldg(&wfq[qk]);
            ull w01 = pack2(w.x, w.y), w23 = pack2(w.z, w.w);
            ulonglong2 hl = hloF[qk];
            ulonglong2 hh = hhiF[qk];
            s0 = ffma2(w01, hl.x, s0); s0 = ffma2(w23, hl.y, s0);
            s1 = ffma2(w01, hh.x, s1); s1 = ffma2(w23, hh.y, s1);
        }
        if (ks) {                                 // publish 10 partials (stride 11)
            myred[0] = red2(ai0); myred[1] = red2(af0);
            myred[2] = red2(ag0); myred[3] = red2(ao0);
            myred[4] = red2(ai1); myred[5] = red2(af1);
            myred[6] = red2(ag1); myred[7] = red2(ao1);
            myred[8] = red2(s0);  myred[9] = red2(s1);
        } else {                                  // ks0 publishes its HI partials
            myred4[0] = red2(ai1); myred4[1] = red2(af1);
            myred4[2] = red2(ag1); myred4[3] = red2(ao1);
            myred4[4] = red2(s1);
        }
        __syncthreads();                          // S1

        const int p1 = (t + 1) & 1;
        if (ks == 0) {                            // owner of LO element (u, gblo)
            const float* r1 = red + prow * REDST;
            const float* r2 = r1 + 128 * REDST;
            const float* r3 = r2 + 128 * REDST;
            float fe = __expf(red2(s0) + r1[8] + r2[8] + r3[8] + bfj);
            float cr = c_lo * fe;                 // deferred fe of previous step
            float gi = red2(ai0) + r1[0] + r2[0] + r3[0] + bias0;
            float gf = red2(af0) + r1[1] + r2[1] + r3[1] + bias1;
            float gg = red2(ag0) + r1[2] + r2[2] + r3[2] + bias2;
            float go = red2(ao0) + r1[3] + r2[3] + r3[3] + bias3;
            float iv = sigm(gi), fv = sigm(gf), gv = tanha(gg), ov = sigm(go);
            c_lo = fv * cr + iv * gv;
            h_lo = ov * tanha(c_lo);
            out[((size_t)gblo * TT + t) * HH + j] = h_lo;
            __stcg(&g_Hbuf[p1][gblo * HH + j], h_lo);
        } else if (ks == 1) {                     // owner of HI element (u, gbhi)
            const float* r2 = red + (128 + prow) * REDST;   // ks=2
            const float* r3 = r2 + 128 * REDST;             // ks=3
            const float* r0 = red4 + prow * RED4ST;         // ks=0 hi
            float fe = __expf(red2(s1) + r0[4] + r2[9] + r3[9] + bfj);
            float cr = c_hi * fe;
            float gi = red2(ai1) + r0[0] + r2[4] + r3[4] + bias0;
            float gf = red2(af1) + r0[1] + r2[5] + r3[5] + bias1;
            float gg = red2(ag1) + r0[2] + r2[6] + r3[6] + bias2;
            float go = red2(ao1) + r0[3] + r2[7] + r3[7] + bias3;
            float iv = sigm(gi), fv = sigm(gf), gv = tanha(gg), ov = sigm(go);
            c_hi = fv * cr + iv * gv;
            h_hi = ov * tanha(c_hi);
            out[((size_t)gbhi * TT + t) * HH + j] = h_hi;
            __stcg(&g_Hbuf[p1][gbhi * HH + j], h_hi);
        }

        // prefetch x_{t+1} (hx.x reads finished at S1)
        if (t + 1 < TT) {
            const float4* xs = (const float4*)x;
            int b = tid >> 5, k4 = tid & 31;      // 512 threads cover UB*II/4
            *(float4*)(hx + b * HXST + k4 * 4) =
                xs[((size_t)(b0 + b) * TT + (t + 1)) * (II / 4) + k4];
        }
        __syncthreads();                          // S2: all h stores issued CTA-wide

        // ===== per-batch-group grid barrier (32 CTAs) =====
        if (tid == 0) {
            __threadfence();                      // release h writes
            atomicAdd(mybar, 1u);
            const unsigned target = (unsigned)(t + 1) * GH;
            while (ld_acq(mybar) < target) { }
        }
        __syncthreads();                          // S3

        // ===== stage h_t into SMEM (vectorized) =====
        {
            const float4* hb = (const float4*)g_Hbuf[p1];
            #pragma unroll
            for (int it = 0; it < (UB * HH / 4) / NTHR; it++) {
                int idx = tid + it * NTHR;
                int b = idx >> 7, k4 = idx & 127;
                float4 v = __ldcg(&hb[(size_t)(b0 + b) * (HH / 4) + k4]);
                *(float4*)(hx + b * HXST + II + k4 * 4) = v;
            }
        }
        __syncthreads();                          // S4
    }

    // ===== epilogue: apply final fe(h_{T-1}) to raw c =====
    {
        ull s0 = 0, s1 = 0;
        #pragma unroll 4
        for (int qk = 0; qk < 32; qk++) {
            float4 w = __ldg(&wfq[qk]);
            ull w01 = pack2(w.x, w.y), w23 = pack2(w.z, w.w);
            ulonglong2 hl = hloF[qk];
            ulonglong2 hh = hhiF[qk];
            s0 = ffma2(w01, hl.x, s0); s0 = ffma2(w23, hl.y, s0);
            s1 = ffma2(w01, hh.x, s1); s1 = ffma2(w23, hh.y, s1);
        }
        if (ks) { myred[8] = red2(s0); myred[9] = red2(s1); }
        else    { myred4[4] = red2(s1); }
        __syncthreads();
        if (ks == 0) {
            const float* r1 = red + prow * REDST;
            const float* r2 = r1 + 128 * REDST;
            const float* r3 = r2 + 128 * REDST;
            c_lo *= __expf(red2(s0) + r1[8] + r2[8] + r3[8] + bfj);
        } else if (ks == 1) {
            const float* r2 = red + (128 + prow) * REDST;
            const float* r3 = r2 + 128 * REDST;
            const float* r0 = red4 + prow * RED4ST;
            c_hi *= __expf(red2(s1) + r0[4] + r2[9] + r3[9] + bfj);
        }
    }

    // ===== final h, c (tuple flatten: out | h | c) =====
    if (out_elems >= (long long)BB * TT * HH + 2LL * BB * HH) {
        float* hout = out + (size_t)BB * TT * HH;
        float* cout = hout + (size_t)BB * HH;
        if (ks == 0) {
            hout[gblo * HH + j] = h_lo;
            cout[gblo * HH + j] = c_lo;
        } else if (ks == 1) {
            hout[gbhi * HH + j] = h_hi;
            cout[gbhi * HH + j] = c_hi;
        }
    }
}

extern "C" void kernel_launch(void* const* d_in, const int* in_sizes, int n_in,
                              void* d_out, int out_size) {
    const float* x    = (const float*)d_in[0];
    const float* W_ih = (const float*)d_in[1];
    const float* W_hh = (const float*)d_in[2];
    const float* b_ih = (const float*)d_in[3];
    const float* b_hh = (const float*)d_in[4];
    const float* Wf   = (const float*)d_in[5];
    const float* bf   = (const float*)d_in[6];
    // d_in[7] = Wi, d_in[8] = bi: unused by the reference recurrence
    float* out = (float*)d_out;

    const size_t smem_bytes =
        (size_t)(64 * WST + UB * HXST + 3 * 128 * REDST + 128 * RED4ST) * sizeof(float);
    // = (41088 + 10304 + 4224 + 896) * 4 = 226,048 B
    cudaFuncSetAttribute(sLSTM_70772471103948_kernel,
                         cudaFuncAttributeMaxDynamicSharedMemorySize, (int)smem_bytes);

    slstm_init_kernel<<<1, 32>>>();
    sLSTM_70772471103948_kernel<<<NCTA, NTHR, smem_bytes>>>(
        x, W_ih, W_hh, b_ih, b_hh, Wf, bf, out, (long long)out_size);
}

// round 15
// speedup vs baseline: 2.7838x; 1.9173x over previous
#include <cuda_runtime.h>
#include <cstddef>

// ---------------- problem constants ----------------
#define BB   64
#define TT   1024
#define II   128
#define HH   512
#define KK   640            // I + H

// ---------------- partitioning ----------------
#define GH   32             // hidden groups
#define GB   4              // batch groups
#define NCTA (GH*GB)        // 128 CTAs, one per SM, all resident
#define UH   16             // hidden units per CTA
#define UB   16             // batches per CTA
#define NTHR 512            // 16 warps: warp = (ug 0..7, bg2 0..1); lane = (ks 0..15, e 0..1)

#define WST  642            // weight row stride (floats), even -> ull rows aligned
#define HXST 644            // hx row stride: 16B-aligned rows

typedef unsigned long long ull;

// persistent state (no cudaMalloc allowed)
__device__ float    g_Hbuf[2][BB*HH];
__device__ unsigned g_bar[GB * 32];   // one counter per batch group, separate lines

// ---------------- packed fp32x2 + fast helpers ----------------
__device__ __forceinline__ ull ffma2(ull a, ull b, ull c) {
    ull d;
    asm("fma.rn.f32x2 %0, %1, %2, %3;" : "=l"(d) : "l"(a), "l"(b), "l"(c));
    return d;
}
__device__ __forceinline__ ull add2(ull a, ull b) {
    ull d;
    asm("add.rn.f32x2 %0, %1, %2;" : "=l"(d) : "l"(a), "l"(b));
    return d;
}
__device__ __forceinline__ float red2(ull v) {
    return __uint_as_float((unsigned)v) + __uint_as_float((unsigned)(v >> 32));
}
__device__ __forceinline__ ull shflx(ull v, int m) {
    unsigned lo = (unsigned)v, hi = (unsigned)(v >> 32);
    lo = __shfl_xor_sync(0xffffffffu, lo, m);
    hi = __shfl_xor_sync(0xffffffffu, hi, m);
    return ((ull)hi << 32) | (ull)lo;
}
__device__ __forceinline__ float tanha(float x) {
    float y; asm("tanh.approx.f32 %0, %1;" : "=f"(y) : "f"(x)); return y;
}
__device__ __forceinline__ float sigm(float x) {
    return fmaf(tanha(0.5f * x), 0.5f, 0.5f);
}
__device__ __forceinline__ unsigned ld_acq(const unsigned* p) {
    unsigned v;
    asm volatile("ld.acquire.gpu.global.u32 %0, [%1];" : "=r"(v) : "l"(p) : "memory");
    return v;
}

__global__ void slstm_init_kernel() {
    if (threadIdx.x < GB) g_bar[threadIdx.x * 32] = 0u;
}

// ---------------- persistent sLSTM kernel ----------------
extern "C" __global__ void __launch_bounds__(NTHR, 1)
sLSTM_70772471103948_kernel(const float* __restrict__ x,     // [B,T,I]
                            const float* __restrict__ W_ih,  // [4H,I]
                            const float* __restrict__ W_hh,  // [4H,H]
                            const float* __restrict__ b_ih,  // [4H]
                            const float* __restrict__ b_hh,  // [4H]
                            const float* __restrict__ Wf,    // [H,H]
                            const float* __restrict__ bf,    // [H]
                            float* __restrict__ out,         // [B,T,H] | h[B,H] | c[B,H]
                            long long out_elems)
{
    extern __shared__ float smem[];
    float* Wsm = smem;                           // 64 rows x WST (gate weights)
    float* hx  = smem + 64 * WST;                // 16 batch rows x HXST ([x_t | h_t])

    const int tid  = threadIdx.x;
    const int w    = tid >> 5;
    const int lane = tid & 31;
    const int ks   = lane & 15;                  // k-slice (strided chunks)
    const int e    = lane >> 4;                  // batch parity
    const int ug   = w & 7;                      // u-pair group (u in {2ug, 2ug+1})
    const int bg2  = w >> 3;                     // batch octet (0/1)
    const int hg   = blockIdx.x & (GH - 1);
    const int bg   = blockIdx.x >> 5;
    const int j0   = hg * UH;
    const int b0   = bg * UB;

    // lane's owned element after shfl reduction: elem = ks>>1 -> (uj, ib)
    const int uj = ks >> 3;
    const int ib = (ks >> 1) & 3;
    const int jl = j0 + 2 * ug + uj;             // owned hidden index
    const int bl = b0 + bg2 * 8 + 2 * ib + e;    // owned global batch

    // ---- stage gate weights into SMEM once ----
    for (int idx = tid; idx < 64 * KK; idx += NTHR) {
        int r  = idx / KK;
        int k  = idx - r * KK;
        int gg = r >> 4, uu = r & 15;
        int grow = gg * HH + j0 + uu;            // gate order: i,f,g,o
        float wv = (k < II) ? W_ih[grow * II + k] : W_hh[grow * HH + (k - II)];
        Wsm[r * WST + k] = wv;
    }
    // ---- stage x_0 ; h_0 = 0 ----
    {
        const float4* xs = (const float4*)x;
        int b = tid >> 5, k4 = tid & 31;          // 512 threads cover UB*II/4
        *(float4*)(hx + b * HXST + k4 * 4) =
            xs[((size_t)(b0 + b) * TT + 0) * (II / 4) + k4];
        float4 z = make_float4(0.f, 0.f, 0.f, 0.f);
        #pragma unroll
        for (int it = 0; it < (UB * HH / 4) / NTHR; it++) {
            int idx = tid + it * NTHR;
            int bb = idx >> 7, kk4 = idx & 127;
            *(float4*)(hx + bb * HXST + II + kk4 * 4) = z;
        }
    }
    const float bias0 = b_ih[0 * HH + jl] + b_hh[0 * HH + jl];
    const float bias1 = b_ih[1 * HH + jl] + b_hh[1 * HH + jl];
    const float bias2 = b_ih[2 * HH + jl] + b_hh[2 * HH + jl];
    const float bias3 = b_ih[3 * HH + jl] + b_hh[3 * HH + jl];
    const float bfj   = bf[jl];

    __syncthreads();

    // base pointers (lane-strided coalesced k)
    const ull* pw  = (const ull*)Wsm + (size_t)ug * WST + ks;            // + (g*16+u2)*321 + m*16
    const ull* pv  = (const ull*)hx + (size_t)(bg2 * 8 + e) * (HXST/2) + ks; // + i*HXST + m*16
    const ull* pwf = (const ull*)(Wf + (size_t)(j0 + 2 * ug) * HH) + ks; // + u2*256 + (m-4)*16

    unsigned* mybar = &g_bar[bg * 32];

    float cc = 0.f, hv = 0.f;                    // owned (jl, bl) state; cc RAW (fe deferred)

    #pragma unroll 1
    for (int t = 0; t < TT; t++) {
        // ===== gates + fused fe over this lane's k-slices =====
        ull acc[32];                             // idx = (uj*4 + i)*4 + g
        ull fac[8];                              // idx = uj*4 + i
        #pragma unroll
        for (int i = 0; i < 32; i++) acc[i] = 0ull;
        #pragma unroll
        for (int i = 0; i < 8; i++) fac[i] = 0ull;

        #pragma unroll
        for (int m = 0; m < 20; m++) {
            ull wr[8];
            #pragma unroll
            for (int g = 0; g < 4; g++) {
                wr[g * 2 + 0] = pw[(g * 16 + 0) * (WST/2) + m * 16];
                wr[g * 2 + 1] = pw[(g * 16 + 1) * (WST/2) + m * 16];
            }
            ull wf0 = 0ull, wf1 = 0ull;
            if (m >= 4) {                        // h-part: fold fe as a 5th gate
                wf0 = __ldg(pwf + (m - 4) * 16);
                wf1 = __ldg(pwf + 256 + (m - 4) * 16);
            }
            #pragma unroll
            for (int i = 0; i < 4; i++) {
                ull v = pv[i * HXST + m * 16];   // batch bg2*8 + 2i + e
                #pragma unroll
                for (int g = 0; g < 4; g++) {
                    acc[(0 * 4 + i) * 4 + g] = ffma2(wr[g * 2 + 0], v, acc[(0 * 4 + i) * 4 + g]);
                    acc[(1 * 4 + i) * 4 + g] = ffma2(wr[g * 2 + 1], v, acc[(1 * 4 + i) * 4 + g]);
                }
                if (m >= 4) {
                    fac[0 * 4 + i] = ffma2(wf0, v, fac[0 * 4 + i]);
                    fac[1 * 4 + i] = ffma2(wf1, v, fac[1 * 4 + i]);
                }
            }
        }

        // ===== intra-warp fold reduction over 16 k-slices =====
        #pragma unroll
        for (int r = 0; r < 4; r++) {
            const int mm = 8 >> r, half = 16 >> r;
            const bool hi = (ks & mm) != 0;
            #pragma unroll
            for (int i = 0; i < half; i++) {
                ull send = hi ? acc[i] : acc[i + half];
                ull recv = shflx(send, mm);
                acc[i] = add2(hi ? acc[i + half] : acc[i], recv);
            }
        }
        #pragma unroll
        for (int r = 0; r < 3; r++) {
            const int mm = 8 >> r, half = 4 >> r;
            const bool hi = (ks & mm) != 0;
            #pragma unroll
            for (int i = 0; i < half; i++) {
                ull send = hi ? fac[i] : fac[i + half];
                ull recv = shflx(send, mm);
                fac[i] = add2(hi ? fac[i + half] : fac[i], recv);
            }
        }
        // lane ks owns gate indices {2ks, 2ks+1}; pair-exchange to get all 4 gates
        ull pa = shflx(acc[0], 1), pb = shflx(acc[1], 1);
        float q0, q1, q2, q3;
        if ((ks & 1) == 0) { q0 = red2(acc[0]); q1 = red2(acc[1]); q2 = red2(pa);     q3 = red2(pb); }
        else               { q0 = red2(pa);     q1 = red2(pb);     q2 = red2(acc[0]); q3 = red2(acc[1]); }
        float fes = red2(fac[0]);
        fes += __shfl_xor_sync(0xffffffffu, fes, 1);

        // ===== deferred fe + activation + state update (dup across lane pair) =====
        float fe = __expf(fes + bfj);
        float cr = cc * fe;                      // fe(h_{t-1}) applied to raw c
        float iv = sigm(q0 + bias0), fv = sigm(q1 + bias1);
        float gv = tanha(q2 + bias2), ov = sigm(q3 + bias3);
        cc = fv * cr + iv * gv;
        hv = ov * tanha(cc);

        const int p1 = (t + 1) & 1;
        if ((ks & 1) == 0) {
            out[((size_t)bl * TT + t) * HH + jl] = hv;
            __stcg(&g_Hbuf[p1][bl * HH + jl], hv);
        }
        __syncthreads();                          // S2: hx reads done; h stores issued

        // prefetch x_{t+1}
        if (t + 1 < TT) {
            const float4* xs = (const float4*)x;
            int b = tid >> 5, k4 = tid & 31;
            *(float4*)(hx + b * HXST + k4 * 4) =
                xs[((size_t)(b0 + b) * TT + (t + 1)) * (II / 4) + k4];
        }
        // ===== per-batch-group grid barrier (32 CTAs) =====
        if (tid == 0) {
            __threadfence();
            atomicAdd(mybar, 1u);
            const unsigned target = (unsigned)(t + 1) * GH;
            while (ld_acq(mybar) < target) { }
        }
        __syncthreads();                          // S3

        // ===== stage h_t into SMEM =====
        {
            const float4* hb = (const float4*)g_Hbuf[p1];
            #pragma unroll
            for (int it = 0; it < (UB * HH / 4) / NTHR; it++) {
                int idx = tid + it * NTHR;
                int b = idx >> 7, k4 = idx & 127;
                float4 v = __ldcg(&hb[(size_t)(b0 + b) * (HH / 4) + k4]);
                *(float4*)(hx + b * HXST + II + k4 * 4) = v;
            }
        }
        __syncthreads();                          // S4
    }

    // ===== epilogue: apply final fe(h_{T-1}) to raw c =====
    {
        ull fac[8];
        #pragma unroll
        for (int i = 0; i < 8; i++) fac[i] = 0ull;
        #pragma unroll
        for (int m = 0; m < 16; m++) {
            ull wf0 = __ldg(pwf + m * 16);
            ull wf1 = __ldg(pwf + 256 + m * 16);
            #pragma unroll
            for (int i = 0; i < 4; i++) {
                ull v = pv[(II / 2) + i * HXST + m * 16];
                fac[0 * 4 + i] = ffma2(wf0, v, fac[0 * 4 + i]);
                fac[1 * 4 + i] = ffma2(wf1, v, fac[1 * 4 + i]);
            }
        }
        #pragma unroll
        for (int r = 0; r < 3; r++) {
            const int mm = 8 >> r, half = 4 >> r;
            const bool hi = (ks & mm) != 0;
            #pragma unroll
            for (int i = 0; i < half; i++) {
                ull send = hi ? fac[i] : fac[i + half];
                ull recv = shflx(send, mm);
                fac[i] = add2(hi ? fac[i + half] : fac[i], recv);
            }
        }
        float fes = red2(fac[0]);
        fes += __shfl_xor_sync(0xffffffffu, fes, 1);
        cc *= __expf(fes + bfj);
    }

    // ===== final h, c (tuple flatten: out | h | c) =====
    if ((ks & 1) == 0 && out_elems >= (long long)BB * TT * HH + 2LL * BB * HH) {
        float* hout = out + (size_t)BB * TT * HH;
        float* cout = hout + (size_t)BB * HH;
        hout[bl * HH + jl] = hv;
        cout[bl * HH + jl] = cc;
    }
}

extern "C" void kernel_launch(void* const* d_in, const int* in_sizes, int n_in,
                              void* d_out, int out_size) {
    const float* x    = (const float*)d_in[0];
    const float* W_ih = (const float*)d_in[1];
    const float* W_hh = (const float*)d_in[2];
    const float* b_ih = (const float*)d_in[3];
    const float* b_hh = (const float*)d_in[4];
    const float* Wf   = (const float*)d_in[5];
    const float* bf   = (const float*)d_in[6];
    // d_in[7] = Wi, d_in[8] = bi: unused by the reference recurrence
    float* out = (float*)d_out;

    const size_t smem_bytes = (size_t)(64 * WST + UB * HXST) * sizeof(float); // 205,568 B
    cudaFuncSetAttribute(sLSTM_70772471103948_kernel,
                         cudaFuncAttributeMaxDynamicSharedMemorySize, (int)smem_bytes);

    slstm_init_kernel<<<1, 32>>>();
    sLSTM_70772471103948_kernel<<<NCTA, NTHR, smem_bytes>>>(
        x, W_ih, W_hh, b_ih, b_hh, Wf, bf, out, (long long)out_size);
}